// round 3
// baseline (speedup 1.0000x reference)
#include <cuda_runtime.h>
#include <cuda_bf16.h>
#include <cstdint>

// ---------------- problem constants ----------------
#define Bb 512
#define Nn 100
#define Tt 100
#define Ee 128
#define HEe 64
#define HDd 256
#define NEe 512
#define Mm (Bb*Nn)            // 51200
#define STEPS 50
// output layout (concatenated float32): x_hat, recon_loss, vq_reduced, indices
#define OFF_RECON  (Mm*Tt)          // 5120000
#define OFF_VQ     (Mm*Tt + 1)
#define OFF_IDX    (Mm*Tt + 2)
#define OUT_FULL   (Mm*Tt + 2 + Mm) // 5171202

typedef unsigned long long u64;

// ---------------- scratch (device globals; no cudaMalloc allowed) ----------------
__device__ __align__(16) float g_z[Mm*Ee];           // 26.2 MB latents
__device__ int   g_idx[Mm];
__device__ __align__(16) float g_w2T[64*3*64];       // [ic][k][oc]
__device__ __align__(16) float g_latT[64*128];       // [oc][e]
__device__ __align__(16) float g_cbP[512*128];       // [(d4*512+e)*4+j] dim-major float4
__device__ float g_cbnorm[512];
__device__ __align__(16) float g_d1T[128*256];       // [k][j]
__device__ __align__(16) float g_d2T[256*256];
__device__ __align__(16) float g_d3T[256*100];
__device__ float g_decoded[513*100];                 // row 512 = zero-input decode
__device__ float g_vqpart[3200];
__device__ float g_rpart[6400*3];

// ---------------- f32x2 helpers ----------------
__device__ __forceinline__ u64 pack2(float a, float b){
    u64 r; asm("mov.b64 %0, {%1,%2};" : "=l"(r) : "f"(a), "f"(b)); return r;
}
__device__ __forceinline__ void ffma2(u64 &d, u64 a, u64 b){
    asm("fma.rn.f32x2 %0, %1, %2, %0;" : "+l"(d) : "l"(a), "l"(b));
}
__device__ __forceinline__ float2 unpack2(u64 v){
    float2 f; asm("mov.b64 {%0,%1}, %2;" : "=f"(f.x), "=f"(f.y) : "l"(v)); return f;
}

// ---------------- prep: layout transposes ----------------
__global__ void prep_kernel(const float* __restrict__ c2w, const float* __restrict__ latw,
                            const float* __restrict__ cb,  const float* __restrict__ d1w,
                            const float* __restrict__ d2w, const float* __restrict__ d3w){
    int gt = blockIdx.x*blockDim.x + threadIdx.x;
    int nt = gridDim.x*blockDim.x;
    // w2T[ic*192 + k*64 + oc] = c2w[oc*192 + ic*3 + k]
    for (int i=gt; i<64*192; i+=nt){
        int oc = i & 63; int r = i >> 6; int k = r % 3; int ic = r / 3;
        g_w2T[i] = c2w[oc*192 + ic*3 + k];
    }
    // latT[oc*128 + e] = latw[e*64 + oc]
    for (int i=gt; i<64*128; i+=nt){
        int e = i & 127; int oc = i >> 7;
        g_latT[i] = latw[e*64 + oc];
    }
    // cbP[(d4*512+e)*4 + j] = cb[e*128 + d4*4 + j]
    for (int i=gt; i<512*128; i+=nt){
        int j = i & 3; int r = i >> 2; int e = r & 511; int d4 = r >> 9;
        g_cbP[i] = cb[e*128 + d4*4 + j];
    }
    for (int e=gt; e<512; e+=nt){
        float s = 0.f;
        for (int d=0; d<128; d++){ float v = cb[e*128+d]; s = fmaf(v,v,s); }
        g_cbnorm[e] = s;
    }
    for (int i=gt; i<128*256; i+=nt){ int j=i&255; int k=i>>8; g_d1T[i] = d1w[j*128+k]; }
    for (int i=gt; i<256*256; i+=nt){ int j=i&255; int k=i>>8; g_d2T[i] = d2w[j*256+k]; }
    for (int i=gt; i<256*100; i+=nt){ int j=i%100; int k=i/100; g_d3T[i] = d3w[j*256+k]; }
}

// ---------------- encoder ----------------
#define HROW 58   // row stride (floats): even (8B-aligned pairs), 232B

template<int NP>
__device__ __forceinline__ float conv2_half(int oc, int l0, u64 bb,
                                            const float* __restrict__ shh,
                                            const float* __restrict__ shs){
    u64 acc[NP];
    #pragma unroll
    for (int p=0;p<NP;p++) acc[p]=bb;
    #pragma unroll 1
    for (int ic=0; ic<64; ic++){
        const float* wr = g_w2T + ic*192 + oc;
        float w0 = wr[0], w1 = wr[64], w2v = wr[128];
        u64 W0 = pack2(w0,w0), W1 = pack2(w1,w1), W2 = pack2(w2v,w2v);
        const float* hr = shh + ic*HROW;
        const float* sr = shs + ic*HROW;
        u64 P0 = *(const u64*)(sr + 2 + l0);
        u64 P1 = *(const u64*)(hr + 2 + l0);
        u64 P2 = *(const u64*)(sr + 4 + l0);
        #pragma unroll
        for (int p=0;p<NP;p++){
            ffma2(acc[p], W0, P0);
            ffma2(acc[p], W1, P1);
            ffma2(acc[p], W2, P2);
            if (p+1 < NP){
                P0 = P2;
                P1 = *(const u64*)(hr + 2 + l0 + 2*(p+1));
                P2 = *(const u64*)(sr + 4 + l0 + 2*(p+1));
            }
        }
    }
    float s = 0.f;
    #pragma unroll
    for (int p=0;p<NP;p++){
        float2 f = unpack2(acc[p]);
        s += fmaxf(f.x,0.f) + fmaxf(f.y,0.f);
    }
    return s;
}

__global__ void __launch_bounds__(128) enc_kernel(const float* __restrict__ x,
                                                  const float* __restrict__ traj,
                                                  const float* __restrict__ imask,
                                                  const float* __restrict__ c1w,
                                                  const float* __restrict__ c1b,
                                                  const float* __restrict__ c2b,
                                                  const float* __restrict__ latb){
    __shared__ __align__(16) float xs[112];
    __shared__ __align__(16) float shh[64*HROW];
    __shared__ __align__(16) float shs[64*HROW];
    __shared__ float phm[2][64];
    __shared__ float hms[64];
    const int m = blockIdx.x;
    const int tid = threadIdx.x;
    const float im = imask[m];
    if (im == 0.f){                     // z = z*im = 0 exactly; skip all compute
        g_z[m*128 + tid] = 0.f;
        return;
    }
    const int oc = tid & 63, half = tid >> 6;
    if (tid < 112){
        float v = 0.f;
        if (tid >= 2 && tid < 102) v = x[m*100 + tid - 2] * traj[m*100 + tid - 2] * im;
        xs[tid] = v;
    }
    // zero pads for the shifted copy (h[-1], h[50])
    if (half == 0) shs[oc*HROW + 2]  = 0.f;
    else           shs[oc*HROW + 53] = 0.f;

    // conv1 weights: out[l] uses xs[2l + j], weight index ic=j&1, k=j>>1
    float w1r[6];
    #pragma unroll
    for (int j=0;j<6;j++) w1r[j] = c1w[oc*6 + (j&1)*3 + (j>>1)];
    const float b1v = c1b[oc];
    __syncthreads();

    const int ls = half ? 26 : 0, le = half ? 50 : 26;
    for (int l=ls; l<le; l++){
        float a = b1v;
        #pragma unroll
        for (int j=0;j<6;j++) a = fmaf(w1r[j], xs[2*l + j], a);
        a = fmaxf(a, 0.f);
        shh[oc*HROW + 2 + l] = a;
        shs[oc*HROW + 3 + l] = a;
    }
    __syncthreads();

    const float b2v = c2b[oc];
    const u64 bb = pack2(b2v, b2v);
    float ssum;
    if (half == 0) ssum = conv2_half<13>(oc, 0,  bb, shh, shs);
    else           ssum = conv2_half<12>(oc, 26, bb, shh, shs);
    phm[half][oc] = ssum;
    __syncthreads();
    if (tid < 64) hms[tid] = (phm[0][tid] + phm[1][tid]) * (1.f/50.f);
    __syncthreads();

    // z[e] = lat_b[e] + sum_oc latT[oc][e] * hm[oc]
    float acc = latb[tid];
    #pragma unroll 4
    for (int o2=0; o2<64; o2++) acc = fmaf(g_latT[o2*128 + tid], hms[o2], acc);
    g_z[m*128 + tid] = acc * im;
}

// ---------------- VQ: batched distances + argmin, reference-matched rounding ----------------
// Reference: d = (znorm - (2*z)@cb.T) + cbn, each op rounded fp32; argmin first-index.
// znorm ~ 11.6 dominates -> d is quantized at ~9.5e-7; near-ties become EXACT ties
// resolved by lowest index. We replicate that quantization exactly.
__global__ void __launch_bounds__(512) vq_kernel(const float* __restrict__ imask){
    __shared__ __align__(16) float zsh[16*128];      // holds 2*z (exact scaling)
    __shared__ u64 smin[16];
    __shared__ float znorm[16];
    __shared__ float vqs[16];
    const int tid = threadIdx.x;
    const int blk = blockIdx.x;
    const int m0 = blk * 16;
    for (int i=tid; i<2048; i+=512) zsh[i] = 2.0f * g_z[m0*128 + i];
    if (tid < 16) smin[tid] = ~0ULL;
    __syncthreads();

    const int wid = tid >> 5, lane = tid & 31;
    { // ||z||^2 per instance: sum((2z)^2)*0.25 has identical rounding to sum(z^2)
        float s = 0.f;
        #pragma unroll
        for (int d=lane; d<128; d+=32){ float v = zsh[wid*128 + d]; s = fmaf(v,v,s); }
        #pragma unroll
        for (int o=16;o;o>>=1) s += __shfl_down_sync(0xFFFFFFFFu, s, o);
        if (lane == 0) znorm[wid] = 0.25f * s;
    }
    __syncthreads();

    const int e = tid;   // 512 entries, one per thread
    u64 acc[16];
    #pragma unroll
    for (int g=0; g<16; g++) acc[g] = 0ULL;
    #pragma unroll 1
    for (int d4=0; d4<32; d4++){
        ulonglong2 cbp = *(const ulonglong2*)(g_cbP + (d4*512 + e)*4);
        #pragma unroll
        for (int g=0; g<16; g++){
            ulonglong2 zz = *(const ulonglong2*)(zsh + g*128 + d4*4);
            ffma2(acc[g], cbp.x, zz.x);
            ffma2(acc[g], cbp.y, zz.y);
        }
    }
    const float cbn = g_cbnorm[e];
    #pragma unroll
    for (int g=0; g<16; g++){
        float2 a = unpack2(acc[g]);
        float dot2 = a.x + a.y;                      // (2z) . cb_e
        float t1 = znorm[g] - dot2;                  // fp32 round (reference order)
        float d  = t1 + cbn;                         // fp32 round -> quantized like ref
        unsigned u = __float_as_uint(d);
        unsigned mono = (u & 0x80000000u) ? ~u : (u | 0x80000000u);
        u64 key = ((u64)mono << 32) | (unsigned)e;   // ties -> smaller e (first min)
        #pragma unroll
        for (int o=16;o;o>>=1){
            u64 other = __shfl_down_sync(0xFFFFFFFFu, key, o);
            key = (other < key) ? other : key;
        }
        if (lane == 0) atomicMin(&smin[g], key);     // integer atomic: deterministic
    }
    __syncthreads();
    if (tid < 16){
        const int g = tid;
        u64 key = smin[g];
        unsigned mono = (unsigned)(key >> 32);
        unsigned u = (mono & 0x80000000u) ? (mono ^ 0x80000000u) : ~mono;
        float d = __uint_as_float(u);                // the (quantized) min distance
        int idx = (int)(key & 0xFFFFFFFFu);
        g_idx[m0 + g] = idx;
        vqs[g] = (1.25f/128.f) * d * imask[m0 + g];  // (beta+1)*mean((z-zq)^2)*im
    }
    __syncthreads();
    if (tid == 0){
        float s = 0.f;
        #pragma unroll
        for (int g=0; g<16; g++) s += vqs[g];
        g_vqpart[blk] = s;
    }
}

// ---------------- decode: 513 distinct inputs only ----------------
__global__ void __launch_bounds__(256) dec_kernel(const float* __restrict__ cb,
                                                  const float* __restrict__ d1b,
                                                  const float* __restrict__ d2b,
                                                  const float* __restrict__ d3b){
    __shared__ float v[128];
    __shared__ float h2[256];
    __shared__ float h3[256];
    const int e = blockIdx.x, tid = threadIdx.x;
    if (tid < 128) v[tid] = (e < 512) ? cb[e*128 + tid] : 0.f;
    __syncthreads();
    float a = d1b[tid];
    #pragma unroll 4
    for (int k=0;k<128;k++) a = fmaf(g_d1T[k*256 + tid], v[k], a);
    h2[tid] = fmaxf(a, 0.f);
    __syncthreads();
    a = d2b[tid];
    #pragma unroll 4
    for (int k=0;k<256;k++) a = fmaf(g_d2T[k*256 + tid], h2[k], a);
    h3[tid] = fmaxf(a, 0.f);
    __syncthreads();
    if (tid < 100){
        a = d3b[tid];
        #pragma unroll 4
        for (int k=0;k<256;k++) a = fmaf(g_d3T[k*100 + tid], h3[k], a);
        g_decoded[e*100 + tid] = a;
    }
}

// ---------------- gather x_hat + masked-MSE partials + indices ----------------
__global__ void __launch_bounds__(256) out_kernel(const float* __restrict__ x,
                                                  const float* __restrict__ traj,
                                                  const float* __restrict__ imask,
                                                  float* __restrict__ out, int full){
    __shared__ float swd[8], sww[8], sim[8];
    const int tid = threadIdx.x, wid = tid >> 5, lane = tid & 31;
    const int m = blockIdx.x*8 + wid;
    const float im = imask[m];
    const int sel = (im > 0.f) ? g_idx[m] : 512;
    const float* dec = g_decoded + sel*100;
    float sdw = 0.f, sw = 0.f;
    for (int t=lane; t<100; t+=32){
        float xh = dec[t];
        float xv = x[m*100 + t];
        float w  = im * traj[m*100 + t];
        out[m*100 + t] = xh;
        float df = xh - xv;
        sdw = fmaf(df*df, w, sdw);
        sw += w;
    }
    #pragma unroll
    for (int o=16;o;o>>=1){
        sdw += __shfl_down_sync(0xFFFFFFFFu, sdw, o);
        sw  += __shfl_down_sync(0xFFFFFFFFu, sw,  o);
    }
    if (lane == 0){
        swd[wid] = sdw; sww[wid] = sw; sim[wid] = im;
        if (full) out[OFF_IDX + m] = (im > 0.f) ? (float)g_idx[m] : -1.0f;
    }
    __syncthreads();
    if (tid == 0){
        float a=0.f,b=0.f,c=0.f;
        #pragma unroll
        for (int w2=0; w2<8; w2++){ a += swd[w2]; b += sww[w2]; c += sim[w2]; }
        g_rpart[blockIdx.x*3 + 0] = a;
        g_rpart[blockIdx.x*3 + 1] = b;
        g_rpart[blockIdx.x*3 + 2] = c;
    }
}

// ---------------- finalize scalars ----------------
__global__ void fin_kernel(float* __restrict__ out, int full){
    __shared__ float sd[256], sw[256], si[256], sv[256];
    const int tid = threadIdx.x;
    float a=0.f,b=0.f,c=0.f,v=0.f;
    for (int i=tid; i<6400; i+=256){
        a += g_rpart[i*3 + 0];
        b += g_rpart[i*3 + 1];
        c += g_rpart[i*3 + 2];
    }
    for (int i=tid; i<3200; i+=256) v += g_vqpart[i];
    sd[tid]=a; sw[tid]=b; si[tid]=c; sv[tid]=v;
    __syncthreads();
    for (int o=128;o;o>>=1){
        if (tid < o){ sd[tid]+=sd[tid+o]; sw[tid]+=sw[tid+o]; si[tid]+=si[tid+o]; sv[tid]+=sv[tid+o]; }
        __syncthreads();
    }
    if (tid == 0 && full){
        out[OFF_RECON] = sd[0] / fmaxf(sw[0], 1.f);
        out[OFF_VQ]    = sv[0] / fmaxf(si[0], 1.f);
    }
}

// ---------------- launch ----------------
extern "C" void kernel_launch(void* const* d_in, const int* in_sizes, int n_in,
                              void* d_out, int out_size){
    const float* x    = (const float*)d_in[0];
    const float* traj = (const float*)d_in[1];
    const float* im   = (const float*)d_in[2];
    const float* c1w  = (const float*)d_in[3];
    const float* c1b  = (const float*)d_in[4];
    const float* c2w  = (const float*)d_in[5];
    const float* c2b  = (const float*)d_in[6];
    const float* latw = (const float*)d_in[7];
    const float* latb = (const float*)d_in[8];
    const float* cb   = (const float*)d_in[9];
    const float* d1w  = (const float*)d_in[10];
    const float* d1b  = (const float*)d_in[11];
    const float* d2w  = (const float*)d_in[12];
    const float* d2b  = (const float*)d_in[13];
    const float* d3w  = (const float*)d_in[14];
    const float* d3b  = (const float*)d_in[15];
    float* out = (float*)d_out;
    const int full = (out_size >= OUT_FULL) ? 1 : 0;

    prep_kernel<<<64, 256>>>(c2w, latw, cb, d1w, d2w, d3w);
    enc_kernel<<<Mm, 128>>>(x, traj, im, c1w, c1b, c2b, latb);
    vq_kernel<<<Mm/16, 512>>>(im);
    dec_kernel<<<513, 256>>>(cb, d1b, d2b, d3b);
    out_kernel<<<Mm/8, 256>>>(x, traj, im, out, full);
    fin_kernel<<<1, 256>>>(out, full);
}

// round 4
// speedup vs baseline: 1.7770x; 1.7770x over previous
#include <cuda_runtime.h>
#include <cuda_bf16.h>
#include <cstdint>

// ---------------- problem constants ----------------
#define Bb 512
#define Nn 100
#define Tt 100
#define Ee 128
#define HEe 64
#define HDd 256
#define NEe 512
#define Mm (Bb*Nn)            // 51200
// output layout (concatenated float32): x_hat, recon_loss, vq_reduced, indices
#define OFF_RECON  (Mm*Tt)          // 5120000
#define OFF_VQ     (Mm*Tt + 1)
#define OFF_IDX    (Mm*Tt + 2)
#define OUT_FULL   (Mm*Tt + 2 + Mm) // 5171202

typedef unsigned long long u64;

// ---------------- scratch (device globals; no cudaMalloc allowed) ----------------
__device__ __align__(16) float g_z[Mm*Ee];           // 26.2 MB latents
__device__ int   g_idx[Mm];
__device__ __align__(16) float2 g_w2P[64*3*32];      // [ic][tap][lane] = {w[oc=lane], w[oc=lane+32]}
__device__ __align__(16) float g_latT[64*128];       // [oc][e]
__device__ __align__(16) float g_cbP[512*128];       // [(d4*512+e)*4+j] dim-major float4
__device__ float g_cbnorm[512];
__device__ __align__(16) float g_d1T[128*256];       // [k][j]
__device__ __align__(16) float g_d2T[256*256];
__device__ __align__(16) float g_d3T[256*100];
__device__ float g_decoded[513*100];                 // row 512 = zero-input decode
__device__ float g_vqpart[3200];
__device__ float g_rpart[6400*3];

// ---------------- f32x2 helpers ----------------
__device__ __forceinline__ u64 pack2(float a, float b){
    u64 r; asm("mov.b64 %0, {%1,%2};" : "=l"(r) : "f"(a), "f"(b)); return r;
}
__device__ __forceinline__ void ffma2(u64 &d, u64 a, u64 b){
    asm("fma.rn.f32x2 %0, %1, %2, %0;" : "+l"(d) : "l"(a), "l"(b));
}
__device__ __forceinline__ float2 unpack2(u64 v){
    float2 f; asm("mov.b64 {%0,%1}, %2;" : "=f"(f.x), "=f"(f.y) : "l"(v)); return f;
}

// ---------------- prep: layout transposes ----------------
__global__ void prep_kernel(const float* __restrict__ c2w, const float* __restrict__ latw,
                            const float* __restrict__ cb,  const float* __restrict__ d1w,
                            const float* __restrict__ d2w, const float* __restrict__ d3w){
    int gt = blockIdx.x*blockDim.x + threadIdx.x;
    int nt = gridDim.x*blockDim.x;
    // w2P[(ic*3+tap)*32 + lane] = {c2w[lane*192+ic*3+tap], c2w[(lane+32)*192+ic*3+tap]}
    for (int i=gt; i<64*3*32; i+=nt){
        int lane = i & 31; int r = i >> 5; int tap = r % 3; int ic = r / 3;
        g_w2P[i] = make_float2(c2w[lane*192 + ic*3 + tap],
                               c2w[(lane+32)*192 + ic*3 + tap]);
    }
    // latT[oc*128 + e] = latw[e*64 + oc]
    for (int i=gt; i<64*128; i+=nt){
        int e = i & 127; int oc = i >> 7;
        g_latT[i] = latw[e*64 + oc];
    }
    // cbP[(d4*512+e)*4 + j] = cb[e*128 + d4*4 + j]
    for (int i=gt; i<512*128; i+=nt){
        int j = i & 3; int r = i >> 2; int e = r & 511; int d4 = r >> 9;
        g_cbP[i] = cb[e*128 + d4*4 + j];
    }
    for (int e=gt; e<512; e+=nt){
        float s = 0.f;
        for (int d=0; d<128; d++){ float v = cb[e*128+d]; s = fmaf(v,v,s); }
        g_cbnorm[e] = s;
    }
    for (int i=gt; i<128*256; i+=nt){ int j=i&255; int k=i>>8; g_d1T[i] = d1w[j*128+k]; }
    for (int i=gt; i<256*256; i+=nt){ int j=i&255; int k=i>>8; g_d2T[i] = d2w[j*256+k]; }
    for (int i=gt; i<256*100; i+=nt){ int j=i%100; int k=i/100; g_d3T[i] = d3w[j*256+k]; }
}

// ---------------- encoder ----------------
#define HROW 56   // row stride (floats): even (8B-aligned pairs), 224B

// Each thread: 2 output channels (lane, lane+32) x NP l-pairs. Warp-uniform value
// loads (broadcast LDS.64), coalesced paired-weight LDG.64. fma-pipe bound.
template<int NP>
__device__ __forceinline__ void conv2_tile(int lane, int l0, u64 bbA, u64 bbB,
                                           const float* __restrict__ shh,
                                           const float* __restrict__ shs,
                                           float &outA, float &outB){
    u64 accA[NP], accB[NP];
    #pragma unroll
    for (int p=0;p<NP;p++){ accA[p]=bbA; accB[p]=bbB; }
    #pragma unroll 2
    for (int ic=0; ic<64; ic++){
        const float2* wp = g_w2P + ic*96;
        float2 w0 = wp[lane], w1 = wp[32+lane], w2 = wp[64+lane];
        u64 W0a = pack2(w0.x,w0.x), W0b = pack2(w0.y,w0.y);
        u64 W1a = pack2(w1.x,w1.x), W1b = pack2(w1.y,w1.y);
        u64 W2a = pack2(w2.x,w2.x), W2b = pack2(w2.y,w2.y);
        const float* hr = shh + ic*HROW + 2 + l0;
        const float* sr = shs + ic*HROW + 2 + l0;
        u64 S0 = *(const u64*)(sr);       // tap0 pair (h[l-1],h[l])
        u64 A0 = *(const u64*)(hr);       // tap1 pair (h[l],h[l+1])
        u64 S1 = *(const u64*)(sr + 2);   // tap2 pair (h[l+1],h[l+2])
        #pragma unroll
        for (int p=0;p<NP;p++){
            ffma2(accA[p], W0a, S0); ffma2(accB[p], W0b, S0);
            ffma2(accA[p], W1a, A0); ffma2(accB[p], W1b, A0);
            ffma2(accA[p], W2a, S1); ffma2(accB[p], W2b, S1);
            if (p+1 < NP){
                S0 = S1;
                A0 = *(const u64*)(hr + 2*(p+1));
                S1 = *(const u64*)(sr + 2*(p+1) + 2);
            }
        }
    }
    float sA = 0.f, sB = 0.f;
    #pragma unroll
    for (int p=0;p<NP;p++){
        float2 fa = unpack2(accA[p]);
        float2 fb = unpack2(accB[p]);
        sA += fmaxf(fa.x,0.f) + fmaxf(fa.y,0.f);
        sB += fmaxf(fb.x,0.f) + fmaxf(fb.y,0.f);
    }
    outA = sA; outB = sB;
}

__global__ void __launch_bounds__(128) enc_kernel(const float* __restrict__ x,
                                                  const float* __restrict__ traj,
                                                  const float* __restrict__ imask,
                                                  const float* __restrict__ c1w,
                                                  const float* __restrict__ c1b,
                                                  const float* __restrict__ c2b,
                                                  const float* __restrict__ latb){
    __shared__ __align__(16) float xs[112];
    __shared__ __align__(16) float shh[64*HROW];
    __shared__ __align__(16) float shs[64*HROW];
    __shared__ float phm[4][64];
    __shared__ float hms[64];
    const int m = blockIdx.x;
    const int tid = threadIdx.x;
    const float im = imask[m];
    if (im == 0.f){                     // z = z*im = 0 exactly; skip all compute
        g_z[m*128 + tid] = 0.f;
        return;
    }
    const int oc = tid & 63, half = tid >> 6;
    if (tid < 112){
        float v = 0.f;
        if (tid >= 2 && tid < 102) v = x[m*100 + tid - 2] * traj[m*100 + tid - 2] * im;
        xs[tid] = v;
    }
    // zero pads for the shifted copy (h[-1], h[50])
    if (half == 0) shs[oc*HROW + 2]  = 0.f;
    else           shs[oc*HROW + 53] = 0.f;

    // conv1 weights: out[l] uses xs[2l + j], weight index ic=j&1, k=j>>1
    float w1r[6];
    #pragma unroll
    for (int j=0;j<6;j++) w1r[j] = c1w[oc*6 + (j&1)*3 + (j>>1)];
    const float b1v = c1b[oc];
    __syncthreads();

    const int ls = half ? 26 : 0, le = half ? 50 : 26;
    for (int l=ls; l<le; l++){
        float a = b1v;
        #pragma unroll
        for (int j=0;j<6;j++) a = fmaf(w1r[j], xs[2*l + j], a);
        a = fmaxf(a, 0.f);
        shh[oc*HROW + 2 + l] = a;
        shs[oc*HROW + 3 + l] = a;
    }
    __syncthreads();

    // conv2: warp w handles pairs {0-6, 7-12, 13-18, 19-24}; thread ocs = (lane, lane+32)
    const int wid = tid >> 5, lane = tid & 31;
    const float bA = c2b[lane], bB = c2b[lane+32];
    const u64 bbA = pack2(bA,bA), bbB = pack2(bB,bB);
    float sA, sB;
    if      (wid == 0) conv2_tile<7>(lane, 0,  bbA, bbB, shh, shs, sA, sB);
    else if (wid == 1) conv2_tile<6>(lane, 14, bbA, bbB, shh, shs, sA, sB);
    else if (wid == 2) conv2_tile<6>(lane, 26, bbA, bbB, shh, shs, sA, sB);
    else               conv2_tile<6>(lane, 38, bbA, bbB, shh, shs, sA, sB);
    phm[wid][lane]      = sA;
    phm[wid][lane + 32] = sB;
    __syncthreads();
    if (tid < 64)
        hms[tid] = (((phm[0][tid] + phm[1][tid]) + phm[2][tid]) + phm[3][tid]) * (1.f/50.f);
    __syncthreads();

    // z[e] = lat_b[e] + sum_oc latT[oc][e] * hm[oc]
    float acc = latb[tid];
    #pragma unroll 4
    for (int o2=0; o2<64; o2++) acc = fmaf(g_latT[o2*128 + tid], hms[o2], acc);
    g_z[m*128 + tid] = acc * im;
}

// ---------------- VQ: batched distances + argmin, reference-matched rounding ----------------
// Reference: d = (znorm - (2*z)@cb.T) + cbn, each op rounded fp32; argmin first-index.
// znorm ~ 11.6 dominates -> d is quantized at ~9.5e-7; near-ties become EXACT ties
// resolved by lowest index. We replicate that quantization exactly.
__global__ void __launch_bounds__(512) vq_kernel(const float* __restrict__ imask){
    __shared__ __align__(16) float zsh[16*128];      // holds 2*z (exact scaling)
    __shared__ u64 smin[16];
    __shared__ float znorm[16];
    __shared__ float vqs[16];
    const int tid = threadIdx.x;
    const int blk = blockIdx.x;
    const int m0 = blk * 16;
    for (int i=tid; i<2048; i+=512) zsh[i] = 2.0f * g_z[m0*128 + i];
    if (tid < 16) smin[tid] = ~0ULL;
    __syncthreads();

    const int wid = tid >> 5, lane = tid & 31;
    { // ||z||^2 per instance: sum((2z)^2)*0.25 has identical rounding to sum(z^2)
        float s = 0.f;
        #pragma unroll
        for (int d=lane; d<128; d+=32){ float v = zsh[wid*128 + d]; s = fmaf(v,v,s); }
        #pragma unroll
        for (int o=16;o;o>>=1) s += __shfl_down_sync(0xFFFFFFFFu, s, o);
        if (lane == 0) znorm[wid] = 0.25f * s;
    }
    __syncthreads();

    const int e = tid;   // 512 entries, one per thread
    u64 acc[16];
    #pragma unroll
    for (int g=0; g<16; g++) acc[g] = 0ULL;
    #pragma unroll 1
    for (int d4=0; d4<32; d4++){
        ulonglong2 cbp = *(const ulonglong2*)(g_cbP + (d4*512 + e)*4);
        #pragma unroll
        for (int g=0; g<16; g++){
            ulonglong2 zz = *(const ulonglong2*)(zsh + g*128 + d4*4);
            ffma2(acc[g], cbp.x, zz.x);
            ffma2(acc[g], cbp.y, zz.y);
        }
    }
    const float cbn = g_cbnorm[e];
    #pragma unroll
    for (int g=0; g<16; g++){
        float2 a = unpack2(acc[g]);
        float dot2 = a.x + a.y;                      // (2z) . cb_e
        float t1 = znorm[g] - dot2;                  // fp32 round (reference order)
        float d  = t1 + cbn;                         // fp32 round -> quantized like ref
        unsigned u = __float_as_uint(d);
        unsigned mono = (u & 0x80000000u) ? ~u : (u | 0x80000000u);
        u64 key = ((u64)mono << 32) | (unsigned)e;   // ties -> smaller e (first min)
        #pragma unroll
        for (int o=16;o;o>>=1){
            u64 other = __shfl_down_sync(0xFFFFFFFFu, key, o);
            key = (other < key) ? other : key;
        }
        if (lane == 0) atomicMin(&smin[g], key);     // integer atomic: deterministic
    }
    __syncthreads();
    if (tid < 16){
        const int g = tid;
        u64 key = smin[g];
        unsigned mono = (unsigned)(key >> 32);
        unsigned u = (mono & 0x80000000u) ? (mono ^ 0x80000000u) : ~mono;
        float d = __uint_as_float(u);                // the (quantized) min distance
        int idx = (int)(key & 0xFFFFFFFFu);
        g_idx[m0 + g] = idx;
        vqs[g] = (1.25f/128.f) * d * imask[m0 + g];  // (beta+1)*mean((z-zq)^2)*im
    }
    __syncthreads();
    if (tid == 0){
        float s = 0.f;
        #pragma unroll
        for (int g=0; g<16; g++) s += vqs[g];
        g_vqpart[blk] = s;
    }
}

// ---------------- decode: 513 distinct inputs only ----------------
__global__ void __launch_bounds__(256) dec_kernel(const float* __restrict__ cb,
                                                  const float* __restrict__ d1b,
                                                  const float* __restrict__ d2b,
                                                  const float* __restrict__ d3b){
    __shared__ float v[128];
    __shared__ float h2[256];
    __shared__ float h3[256];
    const int e = blockIdx.x, tid = threadIdx.x;
    if (tid < 128) v[tid] = (e < 512) ? cb[e*128 + tid] : 0.f;
    __syncthreads();
    float a0=0.f,a1=0.f,a2=0.f,a3=0.f;
    #pragma unroll 4
    for (int k=0;k<128;k+=4){
        a0 = fmaf(g_d1T[(k+0)*256 + tid], v[k+0], a0);
        a1 = fmaf(g_d1T[(k+1)*256 + tid], v[k+1], a1);
        a2 = fmaf(g_d1T[(k+2)*256 + tid], v[k+2], a2);
        a3 = fmaf(g_d1T[(k+3)*256 + tid], v[k+3], a3);
    }
    h2[tid] = fmaxf(d1b[tid] + ((a0+a1)+(a2+a3)), 0.f);
    __syncthreads();
    a0=a1=a2=a3=0.f;
    #pragma unroll 4
    for (int k=0;k<256;k+=4){
        a0 = fmaf(g_d2T[(k+0)*256 + tid], h2[k+0], a0);
        a1 = fmaf(g_d2T[(k+1)*256 + tid], h2[k+1], a1);
        a2 = fmaf(g_d2T[(k+2)*256 + tid], h2[k+2], a2);
        a3 = fmaf(g_d2T[(k+3)*256 + tid], h2[k+3], a3);
    }
    h3[tid] = fmaxf(d2b[tid] + ((a0+a1)+(a2+a3)), 0.f);
    __syncthreads();
    if (tid < 100){
        a0=a1=a2=a3=0.f;
        #pragma unroll 4
        for (int k=0;k<256;k+=4){
            a0 = fmaf(g_d3T[(k+0)*100 + tid], h3[k+0], a0);
            a1 = fmaf(g_d3T[(k+1)*100 + tid], h3[k+1], a1);
            a2 = fmaf(g_d3T[(k+2)*100 + tid], h3[k+2], a2);
            a3 = fmaf(g_d3T[(k+3)*100 + tid], h3[k+3], a3);
        }
        g_decoded[e*100 + tid] = d3b[tid] + ((a0+a1)+(a2+a3));
    }
}

// ---------------- gather x_hat + masked-MSE partials + indices ----------------
__global__ void __launch_bounds__(256) out_kernel(const float* __restrict__ x,
                                                  const float* __restrict__ traj,
                                                  const float* __restrict__ imask,
                                                  float* __restrict__ out, int full){
    __shared__ float swd[8], sww[8], sim[8];
    const int tid = threadIdx.x, wid = tid >> 5, lane = tid & 31;
    const int m = blockIdx.x*8 + wid;
    const float im = imask[m];
    const int sel = (im > 0.f) ? g_idx[m] : 512;
    const float* dec = g_decoded + sel*100;
    float sdw = 0.f, sw = 0.f;
    for (int t=lane; t<100; t+=32){
        float xh = dec[t];
        float xv = x[m*100 + t];
        float w  = im * traj[m*100 + t];
        out[m*100 + t] = xh;
        float df = xh - xv;
        sdw = fmaf(df*df, w, sdw);
        sw += w;
    }
    #pragma unroll
    for (int o=16;o;o>>=1){
        sdw += __shfl_down_sync(0xFFFFFFFFu, sdw, o);
        sw  += __shfl_down_sync(0xFFFFFFFFu, sw,  o);
    }
    if (lane == 0){
        swd[wid] = sdw; sww[wid] = sw; sim[wid] = im;
        if (full) out[OFF_IDX + m] = (im > 0.f) ? (float)g_idx[m] : -1.0f;
    }
    __syncthreads();
    if (tid == 0){
        float a=0.f,b=0.f,c=0.f;
        #pragma unroll
        for (int w2=0; w2<8; w2++){ a += swd[w2]; b += sww[w2]; c += sim[w2]; }
        g_rpart[blockIdx.x*3 + 0] = a;
        g_rpart[blockIdx.x*3 + 1] = b;
        g_rpart[blockIdx.x*3 + 2] = c;
    }
}

// ---------------- finalize scalars ----------------
__global__ void fin_kernel(float* __restrict__ out, int full){
    __shared__ float sd[256], sw[256], si[256], sv[256];
    const int tid = threadIdx.x;
    float a=0.f,b=0.f,c=0.f,v=0.f;
    for (int i=tid; i<6400; i+=256){
        a += g_rpart[i*3 + 0];
        b += g_rpart[i*3 + 1];
        c += g_rpart[i*3 + 2];
    }
    for (int i=tid; i<3200; i+=256) v += g_vqpart[i];
    sd[tid]=a; sw[tid]=b; si[tid]=c; sv[tid]=v;
    __syncthreads();
    for (int o=128;o;o>>=1){
        if (tid < o){ sd[tid]+=sd[tid+o]; sw[tid]+=sw[tid+o]; si[tid]+=si[tid+o]; sv[tid]+=sv[tid+o]; }
        __syncthreads();
    }
    if (tid == 0 && full){
        out[OFF_RECON] = sd[0] / fmaxf(sw[0], 1.f);
        out[OFF_VQ]    = sv[0] / fmaxf(si[0], 1.f);
    }
}

// ---------------- launch ----------------
extern "C" void kernel_launch(void* const* d_in, const int* in_sizes, int n_in,
                              void* d_out, int out_size){
    const float* x    = (const float*)d_in[0];
    const float* traj = (const float*)d_in[1];
    const float* im   = (const float*)d_in[2];
    const float* c1w  = (const float*)d_in[3];
    const float* c1b  = (const float*)d_in[4];
    const float* c2w  = (const float*)d_in[5];
    const float* c2b  = (const float*)d_in[6];
    const float* latw = (const float*)d_in[7];
    const float* latb = (const float*)d_in[8];
    const float* cb   = (const float*)d_in[9];
    const float* d1w  = (const float*)d_in[10];
    const float* d1b  = (const float*)d_in[11];
    const float* d2w  = (const float*)d_in[12];
    const float* d2b  = (const float*)d_in[13];
    const float* d3w  = (const float*)d_in[14];
    const float* d3b  = (const float*)d_in[15];
    float* out = (float*)d_out;
    const int full = (out_size >= OUT_FULL) ? 1 : 0;

    prep_kernel<<<132, 256>>>(c2w, latw, cb, d1w, d2w, d3w);
    enc_kernel<<<Mm, 128>>>(x, traj, im, c1w, c1b, c2b, latb);
    vq_kernel<<<Mm/16, 512>>>(im);
    dec_kernel<<<513, 256>>>(cb, d1b, d2b, d3b);
    out_kernel<<<Mm/8, 256>>>(x, traj, im, out, full);
    fin_kernel<<<1, 256>>>(out, full);
}